// round 11
// baseline (speedup 1.0000x reference)
#include <cuda_runtime.h>
#include <stdint.h>

// Problem constants (fixed by setup_inputs)
#define BB 512        // batch rows
#define NN 100000     // reference points
#define DD 10         // logit dim
#define CC 3072       // x feature dim
#define KNN 50
#define RROWS 8       // rows per CTA tile in main pass (4 packed f32x2 pairs)
#define RGRP (BB / RROWS)   // 64
#define JCH 37        // 64*37 = 2368 CTAs = 8 exact waves @ occ 2 on 148 SMs
#define CAP 8192      // global candidate buffer per row
#define CCAP 128      // per-CTA smem candidate staging per row (exp ~42, 13 sigma margin)
#define TPB 256
#define TROWS 4       // rows per CTA in threshold kernel
#define TSAMP 2048    // sample size (first TSAMP points)
#define TMSEL 32      // threshold = TMSEL-th smallest sample key
#define TIECAP 512
#define PREP_BLOCKS ((NN + TPB - 1) / TPB)   // 391
#define LOGITS_BLOCKS (BB / 8)               // 64 (8 warps per block)

// Scratch (static device globals — allocation-free)
// SoA float4 planes: A = x0..x3, B = x4..x7, C = (x8, x9, xsq, yf).
__device__ float4             g_XA[NN];
__device__ float4             g_XB[NN];
__device__ float4             g_XC[NN];
__device__ float              g_L[BB * DD];
__device__ float              g_scale[BB];
__device__ float              g_T[BB];
__device__ int                g_ccount[BB];
__device__ unsigned long long g_cand[(size_t)BB * CAP]; // 32 MB

// Order-preserving float -> uint map and inverse
__device__ __forceinline__ unsigned mono(float f) {
    unsigned u = __float_as_uint(f);
    return u ^ ((unsigned)((int)u >> 31) | 0x80000000u);
}
__device__ __forceinline__ float unmono(unsigned v) {
    unsigned u = (v & 0x80000000u) ? (v ^ 0x80000000u) : ~v;
    return __uint_as_float(u);
}

// Key: xsq - 2*dot(L,x), fixed fmaf order — SAME chain in every kernel.
// The packed f32x2 path in k_main performs identical per-lane IEEE fma ops in
// the identical order, so keys are bitwise identical everywhere.
__device__ __forceinline__ float keyval(const float* L, const float* xv, float xsq) {
    float acc = 0.f;
#pragma unroll
    for (int c = 0; c < DD; c++) acc = fmaf(L[c], xv[c], acc);
    return fmaf(-2.f, acc, xsq);
}

// Packed f32x2 helpers (Blackwell)
__device__ __forceinline__ unsigned long long pk(float lo, float hi) {
    unsigned long long r;
    asm("mov.b64 %0, {%1, %2};" : "=l"(r) : "f"(lo), "f"(hi));
    return r;
}
__device__ __forceinline__ void fma2(unsigned long long& d, unsigned long long a,
                                     unsigned long long b) {
    asm("fma.rn.f32x2 %0, %1, %2, %0;" : "+l"(d) : "l"(a), "l"(b));
}
__device__ __forceinline__ unsigned long long fma2g(unsigned long long a, unsigned long long b,
                                                    unsigned long long c) {
    unsigned long long d;
    asm("fma.rn.f32x2 %0, %1, %2, %3;" : "=l"(d) : "l"(a), "l"(b), "l"(c));
    return d;
}
__device__ __forceinline__ void upk(float& lo, float& hi, unsigned long long v) {
    asm("mov.b64 {%0, %1}, %2;" : "=f"(lo), "=f"(hi) : "l"(v));
}

// Parallel 256-bin select: find bin b s.t. prefix(b) < remaining <= prefix(b+1).
__device__ __forceinline__ void binselect256(unsigned* hist, unsigned* scanbuf,
                                             int remaining, unsigned* sel, unsigned* run) {
    int tid = threadIdx.x;
    unsigned cnt = (tid < 256) ? hist[tid] : 0u;
    scanbuf[tid] = cnt;
    __syncthreads();
#pragma unroll
    for (int off = 1; off < 256; off <<= 1) {
        unsigned v = (tid >= off && tid < 256) ? scanbuf[tid - off] : 0u;
        __syncthreads();
        if (tid < 256) scanbuf[tid] += v;
        __syncthreads();
    }
    if (tid < 256) {
        unsigned incl = scanbuf[tid];
        unsigned excl = incl - cnt;
        if (excl < (unsigned)remaining && incl >= (unsigned)remaining) {
            *sel = (unsigned)tid;
            *run = excl;
        }
    }
    __syncthreads();
}

// ---------------------------------------------------------------------------
// Kernel 0 (fused): blocks [0,PREP_BLOCKS) pack X into SoA + zero counters;
//                   blocks [PREP_BLOCKS, +LOGITS_BLOCKS) compute logits.
// ---------------------------------------------------------------------------
__global__ void k_setup(const float* __restrict__ X, const int* __restrict__ Y,
                        const float* __restrict__ x, const float* __restrict__ W,
                        const float* __restrict__ bias, float* __restrict__ out) {
    int tid = threadIdx.x;
    if (blockIdx.x < PREP_BLOCKS) {
        int i = blockIdx.x * TPB + tid;
        if (i < BB) g_ccount[i] = 0;
        if (i < NN) {
            float v[DD];
            float xsq = 0.f;
#pragma unroll
            for (int c = 0; c < DD; c++) { v[c] = X[i * DD + c]; xsq = fmaf(v[c], v[c], xsq); }
            g_XA[i] = make_float4(v[0], v[1], v[2], v[3]);
            g_XB[i] = make_float4(v[4], v[5], v[6], v[7]);
            g_XC[i] = make_float4(v[8], v[9], xsq, (float)(2 * Y[i] - 1));
        }
    } else {
        int warp = tid >> 5, lane = tid & 31;
        int row = (blockIdx.x - PREP_BLOCKS) * 8 + warp;
        const float* xr = x + (size_t)row * CC;
        float acc[DD];
#pragma unroll
        for (int c = 0; c < DD; c++) acc[c] = 0.f;
        for (int k = lane; k < CC; k += 32) {
            float xv = xr[k];
            const float* wr = W + (size_t)k * DD;
#pragma unroll
            for (int c = 0; c < DD; c++) acc[c] = fmaf(xv, wr[c], acc[c]);
        }
#pragma unroll
        for (int c = 0; c < DD; c++)
#pragma unroll
            for (int off = 16; off > 0; off >>= 1)
                acc[c] += __shfl_down_sync(0xFFFFFFFFu, acc[c], off);
        if (lane == 0) {
            float mx = 0.f;
#pragma unroll
            for (int c = 0; c < DD; c++) {
                float l = acc[c] + bias[c];
                g_L[row * DD + c] = l;
                out[row * 11 + c] = l;
                mx = fmaxf(mx, fabsf(l));
            }
            g_scale[row] = 2.f * mx;
        }
    }
}

// ---------------------------------------------------------------------------
// Kernel 1: fused sample + threshold — 4 rows/CTA, sample keys in smem,
//           per-row exact radix-select (parallel bin select) -> g_T[row]
// ---------------------------------------------------------------------------
__global__ void k_thresh2() {
    __shared__ unsigned skey[TROWS][TSAMP];   // 32 KB
    __shared__ unsigned hist[256];
    __shared__ unsigned scanbuf[TPB];
    __shared__ unsigned s_sel, s_run;
    int tid = threadIdx.x;
    int row0 = blockIdx.x * TROWS;
    float L[TROWS][DD];
#pragma unroll
    for (int r = 0; r < TROWS; r++)
#pragma unroll
        for (int c = 0; c < DD; c++) L[r][c] = g_L[(row0 + r) * DD + c];
    for (int s = tid; s < TSAMP; s += TPB) {
        float4 a = g_XA[s], b = g_XB[s], c4 = g_XC[s];
        float xv[DD] = {a.x, a.y, a.z, a.w, b.x, b.y, b.z, b.w, c4.x, c4.y};
#pragma unroll
        for (int r = 0; r < TROWS; r++) skey[r][s] = mono(keyval(L[r], xv, c4.z));
    }
    __syncthreads();
    for (int r = 0; r < TROWS; r++) {
        unsigned prefix = 0;
        int remaining = TMSEL;
        for (int pass = 0; pass < 4; pass++) {
            int shift = 24 - 8 * pass;
            unsigned maskhi = pass ? (0xFFFFFFFFu << (32 - 8 * pass)) : 0u;
            if (tid < 256) hist[tid] = 0u;
            __syncthreads();
            for (int i = tid; i < TSAMP; i += TPB) {
                unsigned u = skey[r][i];
                if ((u & maskhi) == prefix) atomicAdd(&hist[(u >> shift) & 255], 1u);
            }
            __syncthreads();
            binselect256(hist, scanbuf, remaining, &s_sel, &s_run);
            remaining -= (int)s_run;
            prefix |= s_sel << shift;
            __syncthreads();
        }
        if (tid == 0) g_T[row0 + r] = unmono(prefix);
        __syncthreads();
    }
}

// ---------------------------------------------------------------------------
// Kernel 2: main pass — packed f32x2 over 4 row-pairs (8 rows/CTA), occ 2,
//           smem candidate staging, one global atomic per row per CTA
// ---------------------------------------------------------------------------
__global__ void __launch_bounds__(TPB, 2) k_main() {
    __shared__ unsigned long long sbuf[RROWS][CCAP];   // 8 KB
    __shared__ int scnt[RROWS];
    __shared__ int sbase[RROWS];
    int tid = threadIdx.x;
    int row0 = blockIdx.x * RROWS;
    if (tid < RROWS) scnt[tid] = 0;
    unsigned long long Lp[RROWS / 2][DD];   // 80 regs
    float Tf[RROWS];
#pragma unroll
    for (int p = 0; p < RROWS / 2; p++)
#pragma unroll
        for (int c = 0; c < DD; c++)
            Lp[p][c] = pk(g_L[(row0 + 2 * p) * DD + c], g_L[(row0 + 2 * p + 1) * DD + c]);
#pragma unroll
    for (int r = 0; r < RROWS; r++) Tf[r] = g_T[row0 + r];
    const unsigned long long M2 = pk(-2.f, -2.f);
    __syncthreads();

    const int chunk = (NN + JCH - 1) / JCH;
    int jbeg = blockIdx.y * chunk;
    int jend = min(NN, jbeg + chunk);

    for (int j = jbeg + tid; j < jend; j += TPB) {
        float4 a = g_XA[j], b = g_XB[j], c4 = g_XC[j];
        unsigned long long xx[DD];
        xx[0] = pk(a.x, a.x); xx[1] = pk(a.y, a.y); xx[2] = pk(a.z, a.z); xx[3] = pk(a.w, a.w);
        xx[4] = pk(b.x, b.x); xx[5] = pk(b.y, b.y); xx[6] = pk(b.z, b.z); xx[7] = pk(b.w, b.w);
        xx[8] = pk(c4.x, c4.x); xx[9] = pk(c4.y, c4.y);
        unsigned long long xs2 = pk(c4.z, c4.z);
#pragma unroll
        for (int p = 0; p < RROWS / 2; p++) {
            unsigned long long acc = 0ull;  // (0.0f, 0.0f)
#pragma unroll
            for (int c = 0; c < DD; c++) fma2(acc, Lp[p][c], xx[c]);
            unsigned long long kk = fma2g(M2, acc, xs2);
            float k0, k1;
            upk(k0, k1, kk);
            if (k0 <= Tf[2 * p]) {
                int slot = atomicAdd(&scnt[2 * p], 1);
                if (slot < CCAP)
                    sbuf[2 * p][slot] = ((unsigned long long)mono(k0) << 32) | (unsigned)j;
            }
            if (k1 <= Tf[2 * p + 1]) {
                int slot = atomicAdd(&scnt[2 * p + 1], 1);
                if (slot < CCAP)
                    sbuf[2 * p + 1][slot] = ((unsigned long long)mono(k1) << 32) | (unsigned)j;
            }
        }
    }
    __syncthreads();

    // Flush: one global atomic per row, coalesced stores.
    if (tid < RROWS) {
        int r = tid;
        int n = scnt[r];
        // overflow (never expected): force ccount > CAP so k_final's fallback recomputes
        int add = (n > CCAP) ? (CAP + 1) : n;
        sbase[r] = atomicAdd(&g_ccount[row0 + r], add);
    }
    __syncthreads();
#pragma unroll
    for (int r = 0; r < RROWS; r++) {
        int n = min(scnt[r], CCAP);
        int base = sbase[r];
        for (int i = tid; i < n; i += TPB) {
            int slot = base + i;
            if (slot < CAP) g_cand[(size_t)(row0 + r) * CAP + slot] = sbuf[r][i];
        }
    }
}

// ---------------------------------------------------------------------------
// Kernel 3: per-row select + vote + adversarial logit. Includes inline exact
//           bisection fallback when the candidate set is bad (never expected).
// ---------------------------------------------------------------------------
__global__ void k_final(float* __restrict__ out) {
    int row = blockIdx.x, tid = threadIdx.x;
    int c = g_ccount[row];
    unsigned long long* cd = &g_cand[(size_t)row * CAP];
    __shared__ unsigned hist[256];
    __shared__ unsigned scanbuf[TPB];
    __shared__ unsigned s_sel, s_run;
    __shared__ int s_refill;

    if (c < KNN || c > CAP) {
        // Exact bisection on mono keys over all N points, then refill g_cand.
        float L[DD];
#pragma unroll
        for (int i = 0; i < DD; i++) L[i] = g_L[row * DD + i];
        __shared__ int scnt2[TPB];
        unsigned lo = 0u, hi = 0xFFFFFFFFu;
        for (int it = 0; it < 32 && lo < hi; it++) {
            unsigned mid = lo + ((hi - lo) >> 1);
            int cnt = 0;
            for (int j = tid; j < NN; j += TPB) {
                float4 a = g_XA[j], b = g_XB[j], c4 = g_XC[j];
                float xv[DD] = {a.x, a.y, a.z, a.w, b.x, b.y, b.z, b.w, c4.x, c4.y};
                cnt += (mono(keyval(L, xv, c4.z)) <= mid);
            }
            scnt2[tid] = cnt;
            __syncthreads();
            for (int st = TPB / 2; st > 0; st >>= 1) {
                if (tid < st) scnt2[tid] += scnt2[tid + st];
                __syncthreads();
            }
            int tot = scnt2[0];
            __syncthreads();
            if (tot >= KNN) hi = mid; else lo = mid + 1;
        }
        if (tid == 0) s_refill = 0;
        __syncthreads();
        for (int j = tid; j < NN; j += TPB) {
            float4 a = g_XA[j], b = g_XB[j], c4 = g_XC[j];
            float xv[DD] = {a.x, a.y, a.z, a.w, b.x, b.y, b.z, b.w, c4.x, c4.y};
            unsigned u = mono(keyval(L, xv, c4.z));
            if (u <= lo) {
                int slot = atomicAdd(&s_refill, 1);
                if (slot < CAP) cd[slot] = ((unsigned long long)u << 32) | (unsigned)j;
            }
        }
        __syncthreads();
        c = min(s_refill, CAP);
    }
    c = min(c, CAP);

    // Exact radix-select of the KNN-th smallest key among candidates.
    unsigned prefix = 0;
    int remaining = KNN;
    for (int pass = 0; pass < 4; pass++) {
        int shift = 24 - 8 * pass;
        unsigned maskhi = pass ? (0xFFFFFFFFu << (32 - 8 * pass)) : 0u;
        if (tid < 256) hist[tid] = 0u;
        __syncthreads();
        for (int i = tid; i < c; i += TPB) {
            unsigned u = (unsigned)(cd[i] >> 32);
            if ((u & maskhi) == prefix) atomicAdd(&hist[(u >> shift) & 255], 1u);
        }
        __syncthreads();
        binselect256(hist, scanbuf, remaining, &s_sel, &s_run);
        remaining -= (int)s_run;
        prefix |= s_sel << shift;
        __syncthreads();
    }
    unsigned k50 = prefix;
    int t = remaining;  // take t smallest-index elements among key==k50 ties

    __shared__ int s_tn;
    __shared__ unsigned tiebuf[TIECAP];
    if (tid == 0) s_tn = 0;
    __syncthreads();
    float local = 0.f;
    for (int i = tid; i < c; i += TPB) {
        unsigned long long v = cd[i];
        unsigned u = (unsigned)(v >> 32);
        unsigned j = (unsigned)(v & 0xFFFFFFFFu);
        if (u < k50) {
            local += g_XC[j].w;  // yf
        } else if (u == k50) {
            int p = atomicAdd(&s_tn, 1);
            if (p < TIECAP) tiebuf[p] = j;
        }
    }
    __syncthreads();
    int nt = min(s_tn, TIECAP);
    for (int i = tid; i < nt; i += TPB) {
        unsigned ji = tiebuf[i];
        int rank = 0;
        for (int k = 0; k < nt; k++) rank += (tiebuf[k] < ji);
        if (rank < t) local += g_XC[ji].w;
    }
    __shared__ float sv[TPB];
    sv[tid] = local;
    __syncthreads();
    for (int st = TPB / 2; st > 0; st >>= 1) {
        if (tid < st) sv[tid] += sv[tid + st];
        __syncthreads();
    }
    if (tid == 0) {
        float v = sv[0];  // + BIAS (= 0)
        float sgn = (v > 0.f) ? 1.f : ((v < 0.f) ? -1.f : 0.f);
        out[row * 11 + 10] = sgn * g_scale[row];
    }
}

// ---------------------------------------------------------------------------
extern "C" void kernel_launch(void* const* d_in, const int* in_sizes, int n_in,
                              void* d_out, int out_size) {
    const float* x    = (const float*)d_in[0];
    const float* W    = (const float*)d_in[1];
    const float* bias = (const float*)d_in[2];
    const float* X    = (const float*)d_in[3];
    const int*   Y    = (const int*)d_in[4];
    float* out = (float*)d_out;

    k_setup<<<PREP_BLOCKS + LOGITS_BLOCKS, TPB>>>(X, Y, x, W, bias, out);
    k_thresh2<<<BB / TROWS, TPB>>>();
    k_main<<<dim3(RGRP, JCH), TPB>>>();
    k_final<<<BB, TPB>>>(out);
}

// round 12
// speedup vs baseline: 1.0531x; 1.0531x over previous
#include <cuda_runtime.h>
#include <stdint.h>

// Problem constants (fixed by setup_inputs)
#define BB 512        // batch rows
#define NN 100000     // reference points
#define DD 10         // logit dim
#define CC 3072       // x feature dim
#define KNN 50
#define RROWS 4       // rows per CTA tile in main pass (low regs -> 4 CTAs/SM)
#define RGRP (BB / RROWS)   // 128
#define JCH 18        // j-chunks: 128*18 = 2304 CTAs
#define CAP 8192      // global candidate buffer per row
#define CCAP 256      // per-CTA smem candidate staging per row (exp ~87, 18 sigma)
#define TPB 256
#define TROWS 4       // rows per CTA in threshold kernel
#define TSAMP 2048    // sample size (first TSAMP points)
#define TMSEL 32      // threshold = TMSEL-th smallest sample key
#define TIECAP 512
#define PREP_BLOCKS ((NN + TPB - 1) / TPB)   // 391
#define LOGITS_BLOCKS (BB / 8)               // 64 (8 warps per block)

// Scratch (static device globals — allocation-free)
// SoA float4 planes: A = x0..x3, B = x4..x7, C = (x8, x9, xsq, yf).
__device__ float4             g_XA[NN];
__device__ float4             g_XB[NN];
__device__ float4             g_XC[NN];
__device__ float              g_L[BB * DD];
__device__ float              g_scale[BB];
__device__ float              g_T[BB];
__device__ int                g_ccount[BB];
__device__ unsigned long long g_cand[(size_t)BB * CAP]; // 32 MB

// Order-preserving float -> uint map and inverse
__device__ __forceinline__ unsigned mono(float f) {
    unsigned u = __float_as_uint(f);
    return u ^ ((unsigned)((int)u >> 31) | 0x80000000u);
}
__device__ __forceinline__ float unmono(unsigned v) {
    unsigned u = (v & 0x80000000u) ? (v ^ 0x80000000u) : ~v;
    return __uint_as_float(u);
}

// Key: xsq - 2*dot(L,x), fixed fmaf order — SAME chain in every kernel,
// so keys are bitwise identical everywhere.
__device__ __forceinline__ float keyval(const float* L, const float* xv, float xsq) {
    float acc = 0.f;
#pragma unroll
    for (int c = 0; c < DD; c++) acc = fmaf(L[c], xv[c], acc);
    return fmaf(-2.f, acc, xsq);
}

// Branchless predicated candidate append: no BSSY/BSYNC envelope.
//   p = (k <= T); @p slot = atomicAdd(cnt); q = p && slot < CCAP;
//   @q st.shared.u64 [buf + slot*8], (mono(k)<<32)|j
__device__ __forceinline__ void append_cand(float k, float T, uint32_t cnt_addr,
                                            uint32_t buf_addr, unsigned j) {
    unsigned long long val = ((unsigned long long)mono(k) << 32) | j;
    asm volatile(
        "{\n\t"
        ".reg .pred p, q;\n\t"
        ".reg .u32 slot, saddr;\n\t"
        "setp.le.f32 p, %0, %1;\n\t"
        "mov.u32 slot, 0;\n\t"
        "@p atom.shared.add.u32 slot, [%2], 1;\n\t"
        "setp.lt.u32 q, slot, %5;\n\t"
        "and.pred q, q, p;\n\t"
        "mad.lo.u32 saddr, slot, 8, %3;\n\t"
        "@q st.shared.u64 [saddr], %4;\n\t"
        "}\n\t"
        :: "f"(k), "f"(T), "r"(cnt_addr), "r"(buf_addr), "l"(val), "n"(CCAP)
        : "memory");
}

// Parallel 256-bin select: find bin b s.t. prefix(b) < remaining <= prefix(b+1).
__device__ __forceinline__ void binselect256(unsigned* hist, unsigned* scanbuf,
                                             int remaining, unsigned* sel, unsigned* run) {
    int tid = threadIdx.x;
    unsigned cnt = (tid < 256) ? hist[tid] : 0u;
    scanbuf[tid] = cnt;
    __syncthreads();
#pragma unroll
    for (int off = 1; off < 256; off <<= 1) {
        unsigned v = (tid >= off && tid < 256) ? scanbuf[tid - off] : 0u;
        __syncthreads();
        if (tid < 256) scanbuf[tid] += v;
        __syncthreads();
    }
    if (tid < 256) {
        unsigned incl = scanbuf[tid];
        unsigned excl = incl - cnt;
        if (excl < (unsigned)remaining && incl >= (unsigned)remaining) {
            *sel = (unsigned)tid;
            *run = excl;
        }
    }
    __syncthreads();
}

// ---------------------------------------------------------------------------
// Kernel 0 (fused): blocks [0,PREP_BLOCKS) pack X into SoA + zero counters;
//                   blocks [PREP_BLOCKS, +LOGITS_BLOCKS) compute logits.
// ---------------------------------------------------------------------------
__global__ void k_setup(const float* __restrict__ X, const int* __restrict__ Y,
                        const float* __restrict__ x, const float* __restrict__ W,
                        const float* __restrict__ bias, float* __restrict__ out) {
    int tid = threadIdx.x;
    if (blockIdx.x < PREP_BLOCKS) {
        int i = blockIdx.x * TPB + tid;
        if (i < BB) g_ccount[i] = 0;
        if (i < NN) {
            float v[DD];
            float xsq = 0.f;
#pragma unroll
            for (int c = 0; c < DD; c++) { v[c] = X[i * DD + c]; xsq = fmaf(v[c], v[c], xsq); }
            g_XA[i] = make_float4(v[0], v[1], v[2], v[3]);
            g_XB[i] = make_float4(v[4], v[5], v[6], v[7]);
            g_XC[i] = make_float4(v[8], v[9], xsq, (float)(2 * Y[i] - 1));
        }
    } else {
        int warp = tid >> 5, lane = tid & 31;
        int row = (blockIdx.x - PREP_BLOCKS) * 8 + warp;
        const float* xr = x + (size_t)row * CC;
        float acc[DD];
#pragma unroll
        for (int c = 0; c < DD; c++) acc[c] = 0.f;
        for (int k = lane; k < CC; k += 32) {
            float xv = xr[k];
            const float* wr = W + (size_t)k * DD;
#pragma unroll
            for (int c = 0; c < DD; c++) acc[c] = fmaf(xv, wr[c], acc[c]);
        }
#pragma unroll
        for (int c = 0; c < DD; c++)
#pragma unroll
            for (int off = 16; off > 0; off >>= 1)
                acc[c] += __shfl_down_sync(0xFFFFFFFFu, acc[c], off);
        if (lane == 0) {
            float mx = 0.f;
#pragma unroll
            for (int c = 0; c < DD; c++) {
                float l = acc[c] + bias[c];
                g_L[row * DD + c] = l;
                out[row * 11 + c] = l;
                mx = fmaxf(mx, fabsf(l));
            }
            g_scale[row] = 2.f * mx;
        }
    }
}

// ---------------------------------------------------------------------------
// Kernel 1: fused sample + threshold — 4 rows/CTA, sample keys in smem,
//           per-row exact radix-select (parallel bin select) -> g_T[row]
// ---------------------------------------------------------------------------
__global__ void k_thresh2() {
    __shared__ unsigned skey[TROWS][TSAMP];   // 32 KB
    __shared__ unsigned hist[256];
    __shared__ unsigned scanbuf[TPB];
    __shared__ unsigned s_sel, s_run;
    int tid = threadIdx.x;
    int row0 = blockIdx.x * TROWS;
    float L[TROWS][DD];
#pragma unroll
    for (int r = 0; r < TROWS; r++)
#pragma unroll
        for (int c = 0; c < DD; c++) L[r][c] = g_L[(row0 + r) * DD + c];
    for (int s = tid; s < TSAMP; s += TPB) {
        float4 a = g_XA[s], b = g_XB[s], c4 = g_XC[s];
        float xv[DD] = {a.x, a.y, a.z, a.w, b.x, b.y, b.z, b.w, c4.x, c4.y};
#pragma unroll
        for (int r = 0; r < TROWS; r++) skey[r][s] = mono(keyval(L[r], xv, c4.z));
    }
    __syncthreads();
    for (int r = 0; r < TROWS; r++) {
        unsigned prefix = 0;
        int remaining = TMSEL;
        for (int pass = 0; pass < 4; pass++) {
            int shift = 24 - 8 * pass;
            unsigned maskhi = pass ? (0xFFFFFFFFu << (32 - 8 * pass)) : 0u;
            if (tid < 256) hist[tid] = 0u;
            __syncthreads();
            for (int i = tid; i < TSAMP; i += TPB) {
                unsigned u = skey[r][i];
                if ((u & maskhi) == prefix) atomicAdd(&hist[(u >> shift) & 255], 1u);
            }
            __syncthreads();
            binselect256(hist, scanbuf, remaining, &s_sel, &s_run);
            remaining -= (int)s_run;
            prefix |= s_sel << shift;
            __syncthreads();
        }
        if (tid == 0) g_T[row0 + r] = unmono(prefix);
        __syncthreads();
    }
}

// ---------------------------------------------------------------------------
// Kernel 2: main pass — scalar FFMA, 4 rows/CTA, 4 CTAs/SM (32 warps),
//           smem staging with BRANCHLESS predicated append (no BSSY/BSYNC)
// ---------------------------------------------------------------------------
__global__ void __launch_bounds__(TPB, 4) k_main() {
    __shared__ unsigned long long sbuf[RROWS][CCAP];   // 8 KB
    __shared__ int scnt[RROWS];
    __shared__ int sbase[RROWS];
    int tid = threadIdx.x;
    int row0 = blockIdx.x * RROWS;
    if (tid < RROWS) scnt[tid] = 0;
    float L[RROWS][DD];
    float Tf[RROWS];
    uint32_t cnt_addr[RROWS], buf_addr[RROWS];
#pragma unroll
    for (int r = 0; r < RROWS; r++) {
        Tf[r] = g_T[row0 + r];
        cnt_addr[r] = (uint32_t)__cvta_generic_to_shared(&scnt[r]);
        buf_addr[r] = (uint32_t)__cvta_generic_to_shared(&sbuf[r][0]);
#pragma unroll
        for (int c = 0; c < DD; c++) L[r][c] = g_L[(row0 + r) * DD + c];
    }
    __syncthreads();

    const int chunk = (NN + JCH - 1) / JCH;
    int jbeg = blockIdx.y * chunk;
    int jend = min(NN, jbeg + chunk);

    for (int j = jbeg + tid; j < jend; j += TPB) {
        float4 a = g_XA[j], b = g_XB[j], c4 = g_XC[j];
        float xv[DD] = {a.x, a.y, a.z, a.w, b.x, b.y, b.z, b.w, c4.x, c4.y};
#pragma unroll
        for (int r = 0; r < RROWS; r++) {
            float k = keyval(L[r], xv, c4.z);
            append_cand(k, Tf[r], cnt_addr[r], buf_addr[r], (unsigned)j);
        }
    }
    __syncthreads();

    // Flush staged candidates: one global atomic per row, coalesced stores.
    if (tid < RROWS) {
        int r = tid;
        int n = scnt[r];
        // overflow (never expected): force ccount > CAP so k_final's fallback recomputes
        int add = (n > CCAP) ? (CAP + 1) : n;
        sbase[r] = atomicAdd(&g_ccount[row0 + r], add);
    }
    __syncthreads();
#pragma unroll
    for (int r = 0; r < RROWS; r++) {
        int n = min(scnt[r], CCAP);
        int base = sbase[r];
        for (int i = tid; i < n; i += TPB) {
            int slot = base + i;
            if (slot < CAP) g_cand[(size_t)(row0 + r) * CAP + slot] = sbuf[r][i];
        }
    }
}

// ---------------------------------------------------------------------------
// Kernel 3: per-row select + vote + adversarial logit. Includes inline exact
//           bisection fallback when the candidate set is bad (never expected).
// ---------------------------------------------------------------------------
__global__ void k_final(float* __restrict__ out) {
    int row = blockIdx.x, tid = threadIdx.x;
    int c = g_ccount[row];
    unsigned long long* cd = &g_cand[(size_t)row * CAP];
    __shared__ unsigned hist[256];
    __shared__ unsigned scanbuf[TPB];
    __shared__ unsigned s_sel, s_run;
    __shared__ int s_refill;

    if (c < KNN || c > CAP) {
        // Exact bisection on mono keys over all N points, then refill g_cand.
        float L[DD];
#pragma unroll
        for (int i = 0; i < DD; i++) L[i] = g_L[row * DD + i];
        __shared__ int scnt2[TPB];
        unsigned lo = 0u, hi = 0xFFFFFFFFu;
        for (int it = 0; it < 32 && lo < hi; it++) {
            unsigned mid = lo + ((hi - lo) >> 1);
            int cnt = 0;
            for (int j = tid; j < NN; j += TPB) {
                float4 a = g_XA[j], b = g_XB[j], c4 = g_XC[j];
                float xv[DD] = {a.x, a.y, a.z, a.w, b.x, b.y, b.z, b.w, c4.x, c4.y};
                cnt += (mono(keyval(L, xv, c4.z)) <= mid);
            }
            scnt2[tid] = cnt;
            __syncthreads();
            for (int st = TPB / 2; st > 0; st >>= 1) {
                if (tid < st) scnt2[tid] += scnt2[tid + st];
                __syncthreads();
            }
            int tot = scnt2[0];
            __syncthreads();
            if (tot >= KNN) hi = mid; else lo = mid + 1;
        }
        if (tid == 0) s_refill = 0;
        __syncthreads();
        for (int j = tid; j < NN; j += TPB) {
            float4 a = g_XA[j], b = g_XB[j], c4 = g_XC[j];
            float xv[DD] = {a.x, a.y, a.z, a.w, b.x, b.y, b.z, b.w, c4.x, c4.y};
            unsigned u = mono(keyval(L, xv, c4.z));
            if (u <= lo) {
                int slot = atomicAdd(&s_refill, 1);
                if (slot < CAP) cd[slot] = ((unsigned long long)u << 32) | (unsigned)j;
            }
        }
        __syncthreads();
        c = min(s_refill, CAP);
    }
    c = min(c, CAP);

    // Exact radix-select of the KNN-th smallest key among candidates.
    unsigned prefix = 0;
    int remaining = KNN;
    for (int pass = 0; pass < 4; pass++) {
        int shift = 24 - 8 * pass;
        unsigned maskhi = pass ? (0xFFFFFFFFu << (32 - 8 * pass)) : 0u;
        if (tid < 256) hist[tid] = 0u;
        __syncthreads();
        for (int i = tid; i < c; i += TPB) {
            unsigned u = (unsigned)(cd[i] >> 32);
            if ((u & maskhi) == prefix) atomicAdd(&hist[(u >> shift) & 255], 1u);
        }
        __syncthreads();
        binselect256(hist, scanbuf, remaining, &s_sel, &s_run);
        remaining -= (int)s_run;
        prefix |= s_sel << shift;
        __syncthreads();
    }
    unsigned k50 = prefix;
    int t = remaining;  // take t smallest-index elements among key==k50 ties

    __shared__ int s_tn;
    __shared__ unsigned tiebuf[TIECAP];
    if (tid == 0) s_tn = 0;
    __syncthreads();
    float local = 0.f;
    for (int i = tid; i < c; i += TPB) {
        unsigned long long v = cd[i];
        unsigned u = (unsigned)(v >> 32);
        unsigned j = (unsigned)(v & 0xFFFFFFFFu);
        if (u < k50) {
            local += g_XC[j].w;  // yf
        } else if (u == k50) {
            int p = atomicAdd(&s_tn, 1);
            if (p < TIECAP) tiebuf[p] = j;
        }
    }
    __syncthreads();
    int nt = min(s_tn, TIECAP);
    for (int i = tid; i < nt; i += TPB) {
        unsigned ji = tiebuf[i];
        int rank = 0;
        for (int k = 0; k < nt; k++) rank += (tiebuf[k] < ji);
        if (rank < t) local += g_XC[ji].w;
    }
    __shared__ float sv[TPB];
    sv[tid] = local;
    __syncthreads();
    for (int st = TPB / 2; st > 0; st >>= 1) {
        if (tid < st) sv[tid] += sv[tid + st];
        __syncthreads();
    }
    if (tid == 0) {
        float v = sv[0];  // + BIAS (= 0)
        float sgn = (v > 0.f) ? 1.f : ((v < 0.f) ? -1.f : 0.f);
        out[row * 11 + 10] = sgn * g_scale[row];
    }
}

// ---------------------------------------------------------------------------
extern "C" void kernel_launch(void* const* d_in, const int* in_sizes, int n_in,
                              void* d_out, int out_size) {
    const float* x    = (const float*)d_in[0];
    const float* W    = (const float*)d_in[1];
    const float* bias = (const float*)d_in[2];
    const float* X    = (const float*)d_in[3];
    const int*   Y    = (const int*)d_in[4];
    float* out = (float*)d_out;

    k_setup<<<PREP_BLOCKS + LOGITS_BLOCKS, TPB>>>(X, Y, x, W, bias, out);
    k_thresh2<<<BB / TROWS, TPB>>>();
    k_main<<<dim3(RGRP, JCH), TPB>>>();
    k_final<<<BB, TPB>>>(out);
}

// round 14
// speedup vs baseline: 1.2720x; 1.2078x over previous
#include <cuda_runtime.h>
#include <stdint.h>

// Problem constants (fixed by setup_inputs)
#define BB 512        // batch rows
#define NN 100000     // reference points
#define DD 10         // logit dim
#define CC 3072       // x feature dim
#define KNN 50
#define RROWS 4       // rows per CTA tile in main pass (low regs -> 4 CTAs/SM)
#define RGRP (BB / RROWS)   // 128
#define JCH 18        // j-chunks: 128*18 = 2304 CTAs
#define CAP 8192      // global candidate buffer per row
#define CCAP 256      // per-CTA smem candidate staging per row (exp ~22)
#define TPB 256
#define TSAMP 4096    // sample size (first TSAMP points)
#define TMSEL 16      // threshold = TMSEL-th smallest sample key (E[cand]~390)
#define TIECAP 512
#define PREP_BLOCKS ((NN + TPB - 1) / TPB)   // 391
#define LOGITS_BLOCKS (BB / 8)               // 64 (8 warps per block)

// Scratch (static device globals — allocation-free)
// SoA float4 planes: A = x0..x3, B = x4..x7, C = (x8, x9, xsq, yf).
__device__ float4             g_XA[NN];
__device__ float4             g_XB[NN];
__device__ float4             g_XC[NN];
__device__ float              g_L[BB * DD];
__device__ float              g_scale[BB];
__device__ float              g_T[BB];
__device__ int                g_ccount[BB];
__device__ unsigned long long g_cand[(size_t)BB * CAP]; // 32 MB

// Order-preserving float -> uint map and inverse
__device__ __forceinline__ unsigned mono(float f) {
    unsigned u = __float_as_uint(f);
    return u ^ ((unsigned)((int)u >> 31) | 0x80000000u);
}
__device__ __forceinline__ float unmono(unsigned v) {
    unsigned u = (v & 0x80000000u) ? (v ^ 0x80000000u) : ~v;
    return __uint_as_float(u);
}

// Key: xsq - 2*dot(L,x), fixed fmaf order — SAME chain in every kernel,
// so keys are bitwise identical everywhere.
__device__ __forceinline__ float keyval(const float* L, const float* xv, float xsq) {
    float acc = 0.f;
#pragma unroll
    for (int c = 0; c < DD; c++) acc = fmaf(L[c], xv[c], acc);
    return fmaf(-2.f, acc, xsq);
}

// Parallel 256-bin select: find bin b s.t. prefix(b) < remaining <= prefix(b+1).
__device__ __forceinline__ void binselect256(unsigned* hist, unsigned* scanbuf,
                                             int remaining, unsigned* sel, unsigned* run) {
    int tid = threadIdx.x;
    unsigned cnt = (tid < 256) ? hist[tid] : 0u;
    scanbuf[tid] = cnt;
    __syncthreads();
#pragma unroll
    for (int off = 1; off < 256; off <<= 1) {
        unsigned v = (tid >= off && tid < 256) ? scanbuf[tid - off] : 0u;
        __syncthreads();
        if (tid < 256) scanbuf[tid] += v;
        __syncthreads();
    }
    if (tid < 256) {
        unsigned incl = scanbuf[tid];
        unsigned excl = incl - cnt;
        if (excl < (unsigned)remaining && incl >= (unsigned)remaining) {
            *sel = (unsigned)tid;
            *run = excl;
        }
    }
    __syncthreads();
}

// ---------------------------------------------------------------------------
// Kernel 0 (fused): blocks [0,PREP_BLOCKS) pack X into SoA (smem-staged,
// coalesced); blocks [PREP_BLOCKS, +LOGITS_BLOCKS) compute logits (float2 W).
// ---------------------------------------------------------------------------
__global__ void k_setup(const float* __restrict__ X, const int* __restrict__ Y,
                        const float* __restrict__ x, const float* __restrict__ W,
                        const float* __restrict__ bias, float* __restrict__ out) {
    int tid = threadIdx.x;
    if (blockIdx.x < PREP_BLOCKS) {
        __shared__ float sX[TPB * DD];   // 10 KB
        int base = blockIdx.x * TPB;
        int nrow = min(TPB, NN - base);
        int nflt = nrow * DD;
        // coalesced global -> smem (1 line per warp-load)
        for (int t = tid; t < nflt; t += TPB) sX[t] = X[(size_t)base * DD + t];
        __syncthreads();
        int i = base + tid;
        if (i < BB) g_ccount[i] = 0;
        if (tid < nrow) {
            float v[DD];
            float xsq = 0.f;
#pragma unroll
            for (int c = 0; c < DD; c++) { v[c] = sX[tid * DD + c]; xsq = fmaf(v[c], v[c], xsq); }
            g_XA[i] = make_float4(v[0], v[1], v[2], v[3]);
            g_XB[i] = make_float4(v[4], v[5], v[6], v[7]);
            g_XC[i] = make_float4(v[8], v[9], xsq, (float)(2 * Y[i] - 1));
        }
    } else {
        int warp = tid >> 5, lane = tid & 31;
        int row = (blockIdx.x - PREP_BLOCKS) * 8 + warp;
        const float* xr = x + (size_t)row * CC;
        float acc[DD];
#pragma unroll
        for (int c = 0; c < DD; c++) acc[c] = 0.f;
        for (int k = lane; k < CC; k += 32) {
            float xv = xr[k];
            const float2* wr = (const float2*)(W + (size_t)k * DD);  // 8B-aligned (40B rows)
            float2 w0 = wr[0], w1 = wr[1], w2 = wr[2], w3 = wr[3], w4 = wr[4];
            acc[0] = fmaf(xv, w0.x, acc[0]); acc[1] = fmaf(xv, w0.y, acc[1]);
            acc[2] = fmaf(xv, w1.x, acc[2]); acc[3] = fmaf(xv, w1.y, acc[3]);
            acc[4] = fmaf(xv, w2.x, acc[4]); acc[5] = fmaf(xv, w2.y, acc[5]);
            acc[6] = fmaf(xv, w3.x, acc[6]); acc[7] = fmaf(xv, w3.y, acc[7]);
            acc[8] = fmaf(xv, w4.x, acc[8]); acc[9] = fmaf(xv, w4.y, acc[9]);
        }
#pragma unroll
        for (int c = 0; c < DD; c++)
#pragma unroll
            for (int off = 16; off > 0; off >>= 1)
                acc[c] += __shfl_down_sync(0xFFFFFFFFu, acc[c], off);
        if (lane == 0) {
            float mx = 0.f;
#pragma unroll
            for (int c = 0; c < DD; c++) {
                float l = acc[c] + bias[c];
                g_L[row * DD + c] = l;
                out[row * 11 + c] = l;
                mx = fmaxf(mx, fabsf(l));
            }
            g_scale[row] = 2.f * mx;
        }
    }
}

// ---------------------------------------------------------------------------
// Kernel 1: threshold — 1 row/CTA, exact radix-select of the TMSEL-th
//           smallest sample key over the first TSAMP points (keys recomputed
//           per pass; sample data is L1/L2-resident) -> g_T[row]
// ---------------------------------------------------------------------------
__global__ void k_thresh2() {
    __shared__ unsigned hist[256];
    __shared__ unsigned scanbuf[TPB];
    __shared__ unsigned s_sel, s_run;
    int tid = threadIdx.x;
    int row = blockIdx.x;
    float L[DD];
#pragma unroll
    for (int c = 0; c < DD; c++) L[c] = g_L[row * DD + c];

    unsigned prefix = 0;
    int remaining = TMSEL;
    for (int pass = 0; pass < 4; pass++) {
        int shift = 24 - 8 * pass;
        unsigned maskhi = pass ? (0xFFFFFFFFu << (32 - 8 * pass)) : 0u;
        if (tid < 256) hist[tid] = 0u;
        __syncthreads();
        for (int s = tid; s < TSAMP; s += TPB) {
            float4 a = g_XA[s], b = g_XB[s], c4 = g_XC[s];
            float xv[DD] = {a.x, a.y, a.z, a.w, b.x, b.y, b.z, b.w, c4.x, c4.y};
            unsigned u = mono(keyval(L, xv, c4.z));
            if ((u & maskhi) == prefix) atomicAdd(&hist[(u >> shift) & 255], 1u);
        }
        __syncthreads();
        binselect256(hist, scanbuf, remaining, &s_sel, &s_run);
        remaining -= (int)s_run;
        prefix |= s_sel << shift;
        __syncthreads();
    }
    if (tid == 0) g_T[row] = unmono(prefix);
}

// ---------------------------------------------------------------------------
// Kernel 2: main pass — scalar FFMA, 4 rows/CTA, 4 CTAs/SM (32 warps),
//           smem candidate staging (R10-proven branchy appends)
// ---------------------------------------------------------------------------
__global__ void __launch_bounds__(TPB, 4) k_main() {
    __shared__ unsigned long long sbuf[RROWS][CCAP];   // 8 KB
    __shared__ int scnt[RROWS];
    __shared__ int sbase[RROWS];
    int tid = threadIdx.x;
    int row0 = blockIdx.x * RROWS;
    if (tid < RROWS) scnt[tid] = 0;
    float L[RROWS][DD];
    float Tf[RROWS];
#pragma unroll
    for (int r = 0; r < RROWS; r++) {
        Tf[r] = g_T[row0 + r];
#pragma unroll
        for (int c = 0; c < DD; c++) L[r][c] = g_L[(row0 + r) * DD + c];
    }
    __syncthreads();

    const int chunk = (NN + JCH - 1) / JCH;
    int jbeg = blockIdx.y * chunk;
    int jend = min(NN, jbeg + chunk);

    for (int j = jbeg + tid; j < jend; j += TPB) {
        float4 a = g_XA[j], b = g_XB[j], c4 = g_XC[j];
        float xv[DD] = {a.x, a.y, a.z, a.w, b.x, b.y, b.z, b.w, c4.x, c4.y};
#pragma unroll
        for (int r = 0; r < RROWS; r++) {
            float k = keyval(L[r], xv, c4.z);
            if (k <= Tf[r]) {
                int slot = atomicAdd(&scnt[r], 1);      // smem atomic: ~35 cyc
                if (slot < CCAP)
                    sbuf[r][slot] = ((unsigned long long)mono(k) << 32) | (unsigned)j;
            }
        }
    }
    __syncthreads();

    // Flush staged candidates: one global atomic per row, coalesced stores.
    if (tid < RROWS) {
        int r = tid;
        int n = scnt[r];
        // overflow (never expected): force ccount > CAP so k_final's fallback recomputes
        int add = (n > CCAP) ? (CAP + 1) : n;
        sbase[r] = atomicAdd(&g_ccount[row0 + r], add);
    }
    __syncthreads();
#pragma unroll
    for (int r = 0; r < RROWS; r++) {
        int n = min(scnt[r], CCAP);
        int base = sbase[r];
        for (int i = tid; i < n; i += TPB) {
            int slot = base + i;
            if (slot < CAP) g_cand[(size_t)(row0 + r) * CAP + slot] = sbuf[r][i];
        }
    }
}

// ---------------------------------------------------------------------------
// Kernel 3: per-row select + vote + adversarial logit. Includes inline exact
//           bisection fallback when the candidate set is bad (never expected).
// ---------------------------------------------------------------------------
__global__ void k_final(float* __restrict__ out) {
    int row = blockIdx.x, tid = threadIdx.x;
    int c = g_ccount[row];
    unsigned long long* cd = &g_cand[(size_t)row * CAP];
    __shared__ unsigned hist[256];
    __shared__ unsigned scanbuf[TPB];
    __shared__ unsigned s_sel, s_run;
    __shared__ int s_refill;

    if (c < KNN || c > CAP) {
        // Exact bisection on mono keys over all N points, then refill g_cand.
        float L[DD];
#pragma unroll
        for (int i = 0; i < DD; i++) L[i] = g_L[row * DD + i];
        __shared__ int scnt2[TPB];
        unsigned lo = 0u, hi = 0xFFFFFFFFu;
        for (int it = 0; it < 32 && lo < hi; it++) {
            unsigned mid = lo + ((hi - lo) >> 1);
            int cnt = 0;
            for (int j = tid; j < NN; j += TPB) {
                float4 a = g_XA[j], b = g_XB[j], c4 = g_XC[j];
                float xv[DD] = {a.x, a.y, a.z, a.w, b.x, b.y, b.z, b.w, c4.x, c4.y};
                cnt += (mono(keyval(L, xv, c4.z)) <= mid);
            }
            scnt2[tid] = cnt;
            __syncthreads();
            for (int st = TPB / 2; st > 0; st >>= 1) {
                if (tid < st) scnt2[tid] += scnt2[tid + st];
                __syncthreads();
            }
            int tot = scnt2[0];
            __syncthreads();
            if (tot >= KNN) hi = mid; else lo = mid + 1;
        }
        if (tid == 0) s_refill = 0;
        __syncthreads();
        for (int j = tid; j < NN; j += TPB) {
            float4 a = g_XA[j], b = g_XB[j], c4 = g_XC[j];
            float xv[DD] = {a.x, a.y, a.z, a.w, b.x, b.y, b.z, b.w, c4.x, c4.y};
            unsigned u = mono(keyval(L, xv, c4.z));
            if (u <= lo) {
                int slot = atomicAdd(&s_refill, 1);
                if (slot < CAP) cd[slot] = ((unsigned long long)u << 32) | (unsigned)j;
            }
        }
        __syncthreads();
        c = min(s_refill, CAP);
    }
    c = min(c, CAP);

    // Exact radix-select of the KNN-th smallest key among candidates.
    unsigned prefix = 0;
    int remaining = KNN;
    for (int pass = 0; pass < 4; pass++) {
        int shift = 24 - 8 * pass;
        unsigned maskhi = pass ? (0xFFFFFFFFu << (32 - 8 * pass)) : 0u;
        if (tid < 256) hist[tid] = 0u;
        __syncthreads();
        for (int i = tid; i < c; i += TPB) {
            unsigned u = (unsigned)(cd[i] >> 32);
            if ((u & maskhi) == prefix) atomicAdd(&hist[(u >> shift) & 255], 1u);
        }
        __syncthreads();
        binselect256(hist, scanbuf, remaining, &s_sel, &s_run);
        remaining -= (int)s_run;
        prefix |= s_sel << shift;
        __syncthreads();
    }
    unsigned k50 = prefix;
    int t = remaining;  // take t smallest-index elements among key==k50 ties

    __shared__ int s_tn;
    __shared__ unsigned tiebuf[TIECAP];
    if (tid == 0) s_tn = 0;
    __syncthreads();
    float local = 0.f;
    for (int i = tid; i < c; i += TPB) {
        unsigned long long v = cd[i];
        unsigned u = (unsigned)(v >> 32);
        unsigned j = (unsigned)(v & 0xFFFFFFFFu);
        if (u < k50) {
            local += g_XC[j].w;  // yf
        } else if (u == k50) {
            int p = atomicAdd(&s_tn, 1);
            if (p < TIECAP) tiebuf[p] = j;
        }
    }
    __syncthreads();
    int nt = min(s_tn, TIECAP);
    for (int i = tid; i < nt; i += TPB) {
        unsigned ji = tiebuf[i];
        int rank = 0;
        for (int k = 0; k < nt; k++) rank += (tiebuf[k] < ji);
        if (rank < t) local += g_XC[ji].w;
    }
    __shared__ float sv[TPB];
    sv[tid] = local;
    __syncthreads();
    for (int st = TPB / 2; st > 0; st >>= 1) {
        if (tid < st) sv[tid] += sv[tid + st];
        __syncthreads();
    }
    if (tid == 0) {
        float v = sv[0];  // + BIAS (= 0)
        float sgn = (v > 0.f) ? 1.f : ((v < 0.f) ? -1.f : 0.f);
        out[row * 11 + 10] = sgn * g_scale[row];
    }
}

// ---------------------------------------------------------------------------
extern "C" void kernel_launch(void* const* d_in, const int* in_sizes, int n_in,
                              void* d_out, int out_size) {
    const float* x    = (const float*)d_in[0];
    const float* W    = (const float*)d_in[1];
    const float* bias = (const float*)d_in[2];
    const float* X    = (const float*)d_in[3];
    const int*   Y    = (const int*)d_in[4];
    float* out = (float*)d_out;

    k_setup<<<PREP_BLOCKS + LOGITS_BLOCKS, TPB>>>(X, Y, x, W, bias, out);
    k_thresh2<<<BB, TPB>>>();
    k_main<<<dim3(RGRP, JCH), TPB>>>();
    k_final<<<BB, TPB>>>(out);
}